// round 16
// baseline (speedup 1.0000x reference)
#include <cuda_runtime.h>
#include <math.h>

// ChamferReward — R15: fused single-matrix chamfer, rt4-aware.
// Model (fits R7/R8/R11/R13 exactly): FFMA2 rt_SMSP=4 -> elapsed = 4*FMA2/jp.
// Only MAC reduction wins; champion computes every d twice. Fused: 512 CTAs
// (one per (b,view)), ITEMS=4, THREADS=256. Per-state: champion chunk-fold +
// bit-identical rescan on unnormalized key t = bb - 2 s.g. Per-goal: full
// d = t + aa tracked THREAD-LOCALLY (gv/gk regs, alu pipe) in the hot loop;
// warp-collective only at chunk end: redux.min + ballot + one-lane atomicMin
// with key (mono(d)<<32 | i) -> exact lex (value, first-index) min.

#define N_PART  1024
#define NJP     512
#define THREADS 256
#define ITEMS   4
#define CJP     8               // jp per chunk (16 goals)
#define NCHUNK  (NJP / CJP)     // 64
#define NCTA    512
#define GPC     (2 * CJP)       // goals per chunk = 16

typedef unsigned long long ull;

__device__ float g_partials[NCTA];
__device__ unsigned int g_arrived = 0;

#define FMA2(d, a, b, c) \
    asm("fma.rn.f32x2 %0, %1, %2, %3;" : "=l"(d) : "l"(a), "l"(b), "l"(c))

__device__ __forceinline__ ull pack_dup(float x) {
    ull r;
    unsigned xi = __float_as_uint(x);
    asm("mov.b64 %0, {%1, %1};" : "=l"(r) : "r"(xi));
    return r;
}

__device__ __forceinline__ void unpack2(ull v, float& lo, float& hi) {
    unsigned a, b;
    asm("mov.b64 {%0, %1}, %2;" : "=r"(a), "=r"(b) : "l"(v));
    lo = __uint_as_float(a);
    hi = __uint_as_float(b);
}

// Order-preserving f32 -> u32 (total order over ordinary floats).
__device__ __forceinline__ unsigned mono_f32(float f) {
    unsigned u = __float_as_uint(f);
    return ((int)u < 0) ? ~u : (u | 0x80000000u);
}
__device__ __forceinline__ float unmono_f32(unsigned m) {
    unsigned u = (m & 0x80000000u) ? (m & 0x7FFFFFFFu) : ~m;
    return __uint_as_float(u);
}

__global__ void __launch_bounds__(THREADS, 2)
chamfer_pass_kernel(const float* __restrict__ achieved,
                    const float* __restrict__ desired,
                    const float* __restrict__ norm_mean,
                    const float* __restrict__ norm_std,
                    float* __restrict__ out)
{
    __shared__ ulonglong2 sb01[NJP];    // 8KB: goal {b0 pair, b1 pair}
    __shared__ ulonglong2 sb23[NJP];    // 8KB: goal {b2 pair, b3 pair}
    __shared__ ull        sbb[NJP];     // 4KB: goal |g|^2 pair
    __shared__ float2     sxy[N_PART];  // 8KB: goal xy
    __shared__ ull        slotj[N_PART];// 8KB: per-goal (mono(d)<<32 | state_i)
    __shared__ float      warp_sums[THREADS / 32];
    __shared__ unsigned int s_rank;

    const int bv = blockIdx.x;          // (b, view)
    const float* ownp = achieved + (size_t)bv * N_PART * 10;  // states (i)
    const float* strp = desired  + (size_t)bv * N_PART * 10;  // goals  (j)

    const float m0 = __ldg(norm_mean + 0), m1 = __ldg(norm_mean + 1);
    const float m5 = __ldg(norm_mean + 5), m6 = __ldg(norm_mean + 6);
    const float m7 = __ldg(norm_mean + 7), m8 = __ldg(norm_mean + 8);
    const float s0 = __ldg(norm_std  + 0), s1 = __ldg(norm_std  + 1);
    const float s5 = __ldg(norm_std  + 5), s6 = __ldg(norm_std  + 6);
    const float s7 = __ldg(norm_std  + 7), s8 = __ldg(norm_std  + 8);

    const int tid  = threadIdx.x;
    const int lane = tid & 31;

    // ---- Stage goals (normalize, |g|^2); init per-goal slots ----
    {
        float* f01 = (float*)sb01;
        float* f23 = (float*)sb23;
        float* fbb = (float*)sbb;
        for (int j = tid; j < N_PART; j += THREADS) {
            const float2* r2 = (const float2*)(strp + (size_t)j * 10);
            const float2 q0 = r2[0];
            const float2 q1 = r2[2];
            const float2 q2 = r2[3];
            const float2 q3 = r2[4];
            float x0 = fmaf(q0.x, s0, m0);
            float x1 = fmaf(q0.y, s1, m1);
            float v0 = fmaf(q1.y, s5, m5);
            float v1 = fmaf(q2.x, s6, m6);
            float v2 = fmaf(q2.y, s7, m7);
            float v3 = fmaf(q3.x, s8, m8);
            const int jp = j >> 1, h = j & 1;
            f01[jp * 4 + h]     = v0;
            f01[jp * 4 + 2 + h] = v1;
            f23[jp * 4 + h]     = v2;
            f23[jp * 4 + 2 + h] = v3;
            fbb[j] = v0 * v0 + v1 * v1 + v2 * v2 + v3 * v3;
            sxy[j] = make_float2(x0, x1);
            slotj[j] = ~0ull;
        }
    }

    // ---- Owned states: i = tid*4 + k (consecutive: lane order == i order) ----
    ull a0d[ITEMS], a1d[ITEMS], a2d[ITEMS], a3d[ITEMS];
    float aa[ITEMS];
#pragma unroll
    for (int k = 0; k < ITEMS; k++) {
        const int i = tid * ITEMS + k;
        const float2* r2 = (const float2*)(ownp + (size_t)i * 10);
        const float2 q1 = r2[2];
        const float2 q2 = r2[3];
        const float2 q3 = r2[4];
        float a0 = fmaf(q1.y, s5, m5);
        float a1 = fmaf(q2.x, s6, m6);
        float a2 = fmaf(q2.y, s7, m7);
        float a3 = fmaf(q3.x, s8, m8);
        aa[k] = a0 * a0 + a1 * a1 + a2 * a2 + a3 * a3;
        a0d[k] = pack_dup(-2.0f * a0);
        a1d[k] = pack_dup(-2.0f * a1);
        a2d[k] = pack_dup(-2.0f * a2);
        a3d[k] = pack_dup(-2.0f * a3);
    }

    __syncthreads();

    // ---- Main loop ----
    float bestd[ITEMS];
    unsigned bcp = 0;               // 4 x 6-bit packed chunk ids
#pragma unroll
    for (int k = 0; k < ITEMS; k++) bestd[k] = 3.4e38f;

    for (int ch = 0; ch < NCHUNK; ch++) {
        float cm[ITEMS];
        float gv[GPC];
        int   gk[GPC];
#pragma unroll
        for (int k = 0; k < ITEMS; k++) cm[k] = 3.4e38f;
#pragma unroll
        for (int g = 0; g < GPC; g++) { gv[g] = 3.4e38f; gk[g] = 0; }

#pragma unroll
        for (int u = 0; u < CJP; u++) {
            const int jp = ch * CJP + u;
            const ulonglong2 p01 = sb01[jp];
            const ulonglong2 p23 = sb23[jp];
            const ull        acc = sbb[jp];
#pragma unroll
            for (int k = 0; k < ITEMS; k++) {
                ull t;
                FMA2(t, a0d[k], p01.x, acc);
                FMA2(t, a1d[k], p01.y, t);
                FMA2(t, a2d[k], p23.x, t);
                FMA2(t, a3d[k], p23.y, t);
                float lo, hi;
                unpack2(t, lo, hi);                   // register-naming only
                // per-state (over goals): unnormalized key, champion mechanics
                cm[k] = fminf(cm[k], fminf(lo, hi));
                // per-goal (over states): full d, ascending k => first-k ties
                const float dlo = lo + aa[k];
                const float dhi = hi + aa[k];
                if (dlo < gv[2 * u])     { gv[2 * u]     = dlo; gk[2 * u]     = k; }
                if (dhi < gv[2 * u + 1]) { gv[2 * u + 1] = dhi; gk[2 * u + 1] = k; }
            }
        }

        // per-state chunk fold: strict < keeps first chunk
#pragma unroll
        for (int k = 0; k < ITEMS; k++) {
            if (cm[k] < bestd[k]) {
                bestd[k] = cm[k];
                bcp = (bcp & ~(63u << (k * 6))) | ((unsigned)ch << (k * 6));
            }
        }

        // per-goal chunk commit: warp redux + first-lane elect + cross-warp
        // atomicMin on (mono(d)<<32 | i): exact lex (value, first-i) min.
#pragma unroll
        for (int g = 0; g < GPC; g++) {
            const int j = ch * GPC + g;
            const unsigned m = mono_f32(gv[g]);
            const unsigned w = __reduce_min_sync(0xffffffffu, m);
            const unsigned ball = __ballot_sync(0xffffffffu, m == w);
            if (lane == __ffs(ball) - 1) {
                const ull key = ((ull)w << 32) | (unsigned)(tid * ITEMS + gk[g]);
                atomicMin(&slotj[j], key);
            }
        }
    }

    // ---- Per-state tail: rescan winner chunk (bit-identical op order) ----
    float partial = 0.0f;
#pragma unroll
    for (int k = 0; k < ITEMS; k++) {
        const int i = tid * ITEMS + k;
        const float2* r2 = (const float2*)(ownp + (size_t)i * 10);
        const float2 q0 = r2[0];
        const float ox = fmaf(q0.x, s0, m0);
        const float oy = fmaf(q0.y, s1, m1);

        const float bd = bestd[k];
        const int jp0 = (int)((bcp >> (k * 6)) & 63u) * CJP;
        int jbest = jp0 * 2;
        bool found = false;
        for (int u = 0; u < CJP; u++) {
            const int jp = jp0 + u;
            const ulonglong2 p01 = sb01[jp];
            const ulonglong2 p23 = sb23[jp];
            const ull        acc = sbb[jp];
            ull t;
            FMA2(t, a0d[k], p01.x, acc);
            FMA2(t, a1d[k], p01.y, t);
            FMA2(t, a2d[k], p23.x, t);
            FMA2(t, a3d[k], p23.y, t);
            float lo, hi;
            unpack2(t, lo, hi);
            if (!found && lo == bd) { jbest = jp * 2;     found = true; }
            if (!found && hi == bd) { jbest = jp * 2 + 1; found = true; }
        }

        const float2 p = sxy[jbest];
        const float dx = ox - p.x;
        const float dy = oy - p.y;
        float xd = sqrtf(dx * dx + dy * dy);
        const float min_d = aa[k] + bd;     // full squared latent distance
        if (min_d > 6.0f) xd = 1.0f;        // LATENT_DIST_THRESHOLD
        partial += xd;
    }

    __syncthreads();   // all per-goal atomics visible

    // ---- Per-goal tail: 4 goals per thread ----
#pragma unroll
    for (int r = 0; r < N_PART / THREADS; r++) {
        const int j = tid * (N_PART / THREADS) + r;
        const ull key = slotj[j];
        const float d = unmono_f32((unsigned)(key >> 32));
        const int i = (int)(key & 0xFFFFFFFFull);
        float xd;
        if (d > 6.0f) {
            xd = 1.0f;
        } else {
            const float2 sq = *(const float2*)(ownp + (size_t)i * 10);
            const float sx = fmaf(sq.x, s0, m0);
            const float sy = fmaf(sq.y, s1, m1);
            const float2 g = sxy[j];
            const float dx = g.x - sx;
            const float dy = g.y - sy;
            xd = sqrtf(dx * dx + dy * dy);
        }
        partial += xd;
    }

    // ---- Block reduce (deterministic) ----
#pragma unroll
    for (int off = 16; off > 0; off >>= 1)
        partial += __shfl_down_sync(0xffffffffu, partial, off);
    if (lane == 0) warp_sums[tid >> 5] = partial;
    __syncthreads();
    if (tid == 0) {
        float s = 0.0f;
#pragma unroll
        for (int w = 0; w < THREADS / 32; w++) s += warp_sums[w];
        g_partials[bv] = s;
        __threadfence();
        s_rank = atomicAdd(&g_arrived, 1u);   // last CTA reduces
    }
    __syncthreads();

    if (s_rank == NCTA - 1) {
        __threadfence();                    // acquire partials
        if (tid < 128) {
            float s = 0.0f;
#pragma unroll
            for (int t = 0; t < 4; t++) s += g_partials[tid * 4 + t];
            out[tid] = -s * (1.0f / (1024.0f * 8.0f));
        }
        __syncthreads();
        if (tid == 0) g_arrived = 0;        // reset for next graph replay
    }
}

extern "C" void kernel_launch(void* const* d_in, const int* in_sizes, int n_in,
                              void* d_out, int out_size)
{
    const float* achieved  = (const float*)d_in[0];
    const float* desired   = (const float*)d_in[1];
    const float* norm_mean = (const float*)d_in[2];
    const float* norm_std  = (const float*)d_in[3];
    float* out = (float*)d_out;

    chamfer_pass_kernel<<<NCTA, THREADS>>>(achieved, desired, norm_mean, norm_std, out);
}